// round 9
// baseline (speedup 1.0000x reference)
#include <cuda_runtime.h>
#include <cuda_bf16.h>

// SNN dense (TTFS) — B=64, IN=1024 (+1 bias row), OUT=1024.
//   K1: stable rank-count sort, 4-way split of the compare range per element
//       (full occupancy); emits packed {x bits, W byte offset}.
//   K2: persistent work-stealing scan; 16 warps split k per item,
//       2 neurons/lane (MBLK=64); clip-free mask math.

#define BATCH 64
#define IN_SZ 1024
#define KTOT 1025          // IN_SZ + bias
#define OUT_SZ 1024
#define MAXT 100000.0f
#define BIASV 1.0f

#define NW 16              // warps (K-chunks) per item
#define CHUNK ((KTOT + NW - 1) / NW)   // 65
#define MBLK 64            // outputs per item (2 per lane)
#define NITEMS (BATCH * (OUT_SZ / MBLK))   // 1024
#define GRID_SCAN 592      // 148 SMs x 4 CTAs

#define SORT_ELEMS 64      // elements ranked per sort CTA
#define SORT_PARTS 4       // compare-range split
#define SORT_BLOCK (SORT_ELEMS * SORT_PARTS)   // 256
#define J2TOT ((KTOT + 1) / 2)                 // 513 ull2 chunks

// Scratch (device globals; no allocation allowed)
__device__ int2 g_pack[BATCH][KTOT + 1];  // {float bits of x, W byte offset}
__device__ unsigned g_ticket;

// ---------------------------------------------------------------------------
// Kernel 1: stable counting sort via packed u64 keys, 4-way range split.
// grid = (17, 64), block = 256. key = (float_bits << 32) | index — positive
// floats order as uints; index tie-break = exact jnp.argsort stability.
// ---------------------------------------------------------------------------
__global__ void __launch_bounds__(SORT_BLOCK) snn_sort_kernel(const float* __restrict__ X) {
    const int b = blockIdx.y;
    __shared__ unsigned long long sk[KTOT + 1];  // +1 pad for ull2 reads
    __shared__ int pr[SORT_ELEMS][SORT_PARTS];

    for (int j = threadIdx.x; j < KTOT; j += SORT_BLOCK) {
        float v = (j < IN_SZ) ? X[b * IN_SZ + j] : BIASV;
        sk[j] = ((unsigned long long)__float_as_uint(v) << 32) | (unsigned)j;
    }
    if (threadIdx.x == 0) {
        sk[KTOT] = ~0ull;                              // pad: never counted
        if (blockIdx.x == 0 && b == 0) g_ticket = 0;   // reset work queue
        int2 s; s.x = __float_as_int(MAXT); s.y = 0;
        if (blockIdx.x == 0) g_pack[b][KTOT] = s;      // next_x sentinel
    }
    __syncthreads();

    const int li   = threadIdx.x & (SORT_ELEMS - 1);
    const int part = threadIdx.x >> 6;
    const int i    = blockIdx.x * SORT_ELEMS + li;
    const bool valid = (i < KTOT);

    const unsigned long long ki = valid ? sk[i] : ~0ull;
    const int lo = (J2TOT * part) / SORT_PARTS;
    const int hi = (J2TOT * (part + 1)) / SORT_PARTS;

    int r = 0;
    const ulonglong2* sk2 = reinterpret_cast<const ulonglong2*>(sk);
    #pragma unroll 4
    for (int j2 = lo; j2 < hi; ++j2) {
        ulonglong2 v = sk2[j2];
        r += (v.x < ki);
        r += (v.y < ki);
    }
    pr[li][part] = r;
    __syncthreads();

    if (part == 0 && valid) {
        int rank = pr[li][0] + pr[li][1] + pr[li][2] + pr[li][3];
        int2 p;
        p.x = (int)(ki >> 32);                              // float bits of x
        p.y = ((int)(ki & 0xFFFFFFFFu)) * (OUT_SZ * 4);     // W row byte off
        g_pack[b][rank] = p;
    }
}

// ---------------------------------------------------------------------------
// Kernel 2: persistent work-stealing scan. grid = 592, block = 512.
// Item = (b, m-block of 64). Warp w owns k in [w*CHUNK, ...); lane L owns
// outputs mbase + 2L, 2L+1. cw starts at -1 (threshold folded); no EPS
// clip: cand = ct * RCP(cw); inf/NaN corner cases fall out via the range
// checks and NaN-ignoring fminf.
// ---------------------------------------------------------------------------
__global__ void __launch_bounds__(512, 4) snn_scan_kernel(const float* __restrict__ W,
                                                          float* __restrict__ out) {
    __shared__ int2  sp[KTOT + 1];
    __shared__ float pw[NW][MBLK];
    __shared__ float pt[NW][MBLK];
    __shared__ float pm[NW][MBLK];
    __shared__ unsigned s_item;

    const int w    = threadIdx.x >> 5;
    const int lane = threadIdx.x & 31;
    const int k0 = w * CHUNK;
    const int k1 = (k0 + CHUNK < KTOT) ? (k0 + CHUNK) : KTOT;

    for (;;) {
        if (threadIdx.x == 0) s_item = atomicAdd(&g_ticket, 1u);
        __syncthreads();
        const unsigned item = s_item;
        if (item >= NITEMS) return;

        const int b     = item >> 4;            // item / (OUT_SZ/MBLK)
        const int mbase = (item & 15) * MBLK;

        for (int j = threadIdx.x; j < KTOT + 1; j += blockDim.x)
            sp[j] = g_pack[b][j];
        __syncthreads();

        const char* Wb = (const char*)W + (size_t)(mbase + 2 * lane) * 4;

        // ---- pass 1: chunk partial sums ----
        float s0 = 0.f, t0 = 0.f, s1 = 0.f, t1 = 0.f;
        #pragma unroll 4
        for (int k = k0; k < k1; ++k) {
            const int2 p = sp[k];
            const float x = __int_as_float(p.x);
            const float2 wv = *reinterpret_cast<const float2*>(Wb + p.y);
            s0 += wv.x; t0 = fmaf(wv.x, x, t0);
            s1 += wv.y; t1 = fmaf(wv.y, x, t1);
        }
        pw[w][2 * lane] = s0;     pt[w][2 * lane] = t0;
        pw[w][2 * lane + 1] = s1; pt[w][2 * lane + 1] = t1;
        __syncthreads();

        // ---- exclusive prefix (threshold folded: start at -1) ----
        float cw0 = -1.f, ct0 = 0.f, cw1 = -1.f, ct1 = 0.f;
        for (int c = 0; c < w; ++c) {
            cw0 += pw[c][2 * lane];     ct0 += pt[c][2 * lane];
            cw1 += pw[c][2 * lane + 1]; ct1 += pt[c][2 * lane + 1];
        }

        // ---- pass 2: scan chunk, evaluate candidates ----
        float best0 = MAXT, best1 = MAXT;
        int2 pc = sp[k0];
        #pragma unroll 4
        for (int k = k0; k < k1; ++k) {
            const float x = __int_as_float(pc.x);
            const int off = pc.y;
            pc = sp[k + 1];
            const float nx = __int_as_float(pc.x);
            const float2 wv = *reinterpret_cast<const float2*>(Wb + off);

            cw0 += wv.x; ct0 = fmaf(wv.x, x, ct0);
            {
                float cand = __fdividef(ct0, cw0);
                bool bad = (cw0 < 0.f) | (cand < x) | (cand > nx);
                if (!bad) best0 = fminf(best0, cand);
            }
            cw1 += wv.y; ct1 = fmaf(wv.y, x, ct1);
            {
                float cand = __fdividef(ct1, cw1);
                bool bad = (cw1 < 0.f) | (cand < x) | (cand > nx);
                if (!bad) best1 = fminf(best1, cand);
            }
        }
        pm[w][2 * lane]     = best0;
        pm[w][2 * lane + 1] = best1;
        __syncthreads();

        // ---- final min across chunks ----
        if (threadIdx.x < MBLK) {
            float bb = MAXT;
            #pragma unroll
            for (int c = 0; c < NW; ++c)
                bb = fminf(bb, pm[c][threadIdx.x]);
            out[b * OUT_SZ + mbase + threadIdx.x] = bb;
        }
        __syncthreads();   // protect sp/pm/s_item before next item
    }
}

// ---------------------------------------------------------------------------
extern "C" void kernel_launch(void* const* d_in, const int* in_sizes, int n_in,
                              void* d_out, int out_size) {
    const float* X = (const float*)d_in[0];
    const float* W = (const float*)d_in[1];
    if (n_in >= 2 && in_sizes[0] != BATCH * IN_SZ && in_sizes[1] == BATCH * IN_SZ) {
        X = (const float*)d_in[1];
        W = (const float*)d_in[0];
    }
    float* out = (float*)d_out;

    dim3 gs((KTOT + SORT_ELEMS - 1) / SORT_ELEMS, BATCH);   // (17, 64)
    snn_sort_kernel<<<gs, SORT_BLOCK>>>(X);

    snn_scan_kernel<<<GRID_SCAN, 512>>>(W, out);
}

// round 10
// speedup vs baseline: 1.0475x; 1.0475x over previous
#include <cuda_runtime.h>
#include <cuda_bf16.h>

// SNN dense (TTFS) — B=64, IN=1024 (+1 bias row), OUT=1024.
//   K1: stable rank-count sort, 4-way split of the compare range per element.
//   K2: persistent work-stealing scan; 16 warps split k per item, 2 neurons
//       per lane; packed f32x2 accumulators (bit-identical per-component);
//       R8 eval (clip + fast-div + select); redundant cw<0 setp dropped in
//       the main loop (provably inert except final k, which is peeled).

#define BATCH 64
#define IN_SZ 1024
#define KTOT 1025          // IN_SZ + bias
#define OUT_SZ 1024
#define MAXT 100000.0f
#define EPSV 1e-10f
#define BIASV 1.0f

#define NW 16              // warps (K-chunks) per item
#define CHUNK ((KTOT + NW - 1) / NW)   // 65
#define MBLK 64            // outputs per item (2 per lane)
#define NITEMS (BATCH * (OUT_SZ / MBLK))   // 1024
#define GRID_SCAN 592      // 148 SMs x 4 CTAs

#define SORT_ELEMS 64
#define SORT_PARTS 4
#define SORT_BLOCK (SORT_ELEMS * SORT_PARTS)   // 256
#define J2TOT ((KTOT + 1) / 2)                 // 513 ull2 chunks

typedef unsigned long long ull;

// packed f32x2 helpers (sm_103a FFMA2/FADD2 — only reachable via PTX)
__device__ __forceinline__ ull f2_add(ull a, ull b) {
    ull r; asm("add.rn.f32x2 %0,%1,%2;" : "=l"(r) : "l"(a), "l"(b)); return r;
}
__device__ __forceinline__ ull f2_fma(ull a, ull b, ull c) {
    ull r; asm("fma.rn.f32x2 %0,%1,%2,%3;" : "=l"(r) : "l"(a), "l"(b), "l"(c)); return r;
}
__device__ __forceinline__ ull f2_bcast(float x) {
    ull r; asm("mov.b64 %0,{%1,%1};" : "=l"(r) : "f"(x)); return r;
}
__device__ __forceinline__ void f2_unpack(float& lo, float& hi, ull v) {
    asm("mov.b64 {%0,%1},%2;" : "=f"(lo), "=f"(hi) : "l"(v));
}

// Scratch (device globals; no allocation allowed)
__device__ int2 g_pack[BATCH][KTOT + 1];  // {float bits of x, W byte offset}
__device__ unsigned g_ticket;

// ---------------------------------------------------------------------------
// Kernel 1: stable counting sort via packed u64 keys, 4-way range split.
// ---------------------------------------------------------------------------
__global__ void __launch_bounds__(SORT_BLOCK) snn_sort_kernel(const float* __restrict__ X) {
    const int b = blockIdx.y;
    __shared__ ull sk[KTOT + 1];
    __shared__ int pr[SORT_ELEMS][SORT_PARTS];

    for (int j = threadIdx.x; j < KTOT; j += SORT_BLOCK) {
        float v = (j < IN_SZ) ? X[b * IN_SZ + j] : BIASV;
        sk[j] = ((ull)__float_as_uint(v) << 32) | (unsigned)j;
    }
    if (threadIdx.x == 0) {
        sk[KTOT] = ~0ull;
        if (blockIdx.x == 0 && b == 0) g_ticket = 0;
        int2 s; s.x = __float_as_int(MAXT); s.y = 0;
        if (blockIdx.x == 0) g_pack[b][KTOT] = s;      // next_x sentinel
    }
    __syncthreads();

    const int li   = threadIdx.x & (SORT_ELEMS - 1);
    const int part = threadIdx.x >> 6;
    const int i    = blockIdx.x * SORT_ELEMS + li;
    const bool valid = (i < KTOT);

    const ull ki = valid ? sk[i] : ~0ull;
    const int lo = (J2TOT * part) / SORT_PARTS;
    const int hi = (J2TOT * (part + 1)) / SORT_PARTS;

    int r = 0;
    const ulonglong2* sk2 = reinterpret_cast<const ulonglong2*>(sk);
    #pragma unroll 4
    for (int j2 = lo; j2 < hi; ++j2) {
        ulonglong2 v = sk2[j2];
        r += (v.x < ki);
        r += (v.y < ki);
    }
    pr[li][part] = r;
    __syncthreads();

    if (part == 0 && valid) {
        int rank = pr[li][0] + pr[li][1] + pr[li][2] + pr[li][3];
        int2 p;
        p.x = (int)(ki >> 32);
        p.y = ((int)(ki & 0xFFFFFFFFu)) * (OUT_SZ * 4);
        g_pack[b][rank] = p;
    }
}

// ---------------------------------------------------------------------------
// Kernel 2: persistent work-stealing scan. grid = 592, block = 512.
// ---------------------------------------------------------------------------
__global__ void __launch_bounds__(512, 4) snn_scan_kernel(const float* __restrict__ W,
                                                          float* __restrict__ out) {
    __shared__ int2  sp[KTOT + 1];
    __shared__ ull   pw[NW][32];     // packed chunk sums of w
    __shared__ ull   pt[NW][32];     // packed chunk sums of w*x
    __shared__ float pm[NW][MBLK];   // per-chunk minima
    __shared__ unsigned s_item;

    const int w    = threadIdx.x >> 5;
    const int lane = threadIdx.x & 31;
    const int k0 = w * CHUNK;
    const int k1 = (k0 + CHUNK < KTOT) ? (k0 + CHUNK) : KTOT;
    const int k1m = (w == NW - 1) ? (KTOT - 1) : k1;   // peel final k

    for (;;) {
        if (threadIdx.x == 0) s_item = atomicAdd(&g_ticket, 1u);
        __syncthreads();
        const unsigned item = s_item;
        if (item >= NITEMS) return;

        const int b     = item >> 4;
        const int mbase = (item & 15) * MBLK;

        for (int j = threadIdx.x; j < KTOT + 1; j += blockDim.x)
            sp[j] = g_pack[b][j];
        __syncthreads();

        const char* Wb = (const char*)W + (size_t)(mbase + 2 * lane) * 4;

        // ---- pass 1: packed chunk partial sums ----
        ull s2 = 0ull, t2 = 0ull;
        #pragma unroll 4
        for (int k = k0; k < k1; ++k) {
            const int2 p = sp[k];
            const ull w2 = *reinterpret_cast<const ull*>(Wb + p.y);
            const ull x2 = f2_bcast(__int_as_float(p.x));
            s2 = f2_add(s2, w2);
            t2 = f2_fma(w2, x2, t2);
        }
        pw[w][lane] = s2;
        pt[w][lane] = t2;
        __syncthreads();

        // ---- exclusive prefix (threshold folded: start at -1) ----
        ull cw2 = 0xBF800000BF800000ull;   // (-1.f, -1.f)
        ull ct2 = 0ull;
        for (int c = 0; c < w; ++c) {
            cw2 = f2_add(cw2, pw[c][lane]);
            ct2 = f2_add(ct2, pt[c][lane]);
        }

        // ---- pass 2: scan chunk, evaluate candidates ----
        float best0 = MAXT, best1 = MAXT;
        int2 pc = sp[k0];
        #pragma unroll 4
        for (int k = k0; k < k1m; ++k) {
            const float x  = __int_as_float(pc.x);
            const int  off = pc.y;
            pc = sp[k + 1];
            const float nx = __int_as_float(pc.x);
            const ull w2 = *reinterpret_cast<const ull*>(Wb + off);

            cw2 = f2_add(cw2, w2);
            ct2 = f2_fma(w2, f2_bcast(x), ct2);
            float cw0, cw1, ct0, ct1;
            f2_unpack(cw0, cw1, cw2);
            f2_unpack(ct0, ct1, ct2);
            // cw<0 check dropped: with den=max(cw,EPS), cw<0 forces
            // cand=ct/1e-10 outside [x,nx] (nx<=2 here) except measure-zero.
            {
                float cand = __fdividef(ct0, fmaxf(cw0, EPSV));
                bool bad = (cand < x) | (cand > nx);
                best0 = fminf(best0, bad ? MAXT : cand);
            }
            {
                float cand = __fdividef(ct1, fmaxf(cw1, EPSV));
                bool bad = (cand < x) | (cand > nx);
                best1 = fminf(best1, bad ? MAXT : cand);
            }
        }
        // ---- peeled final k (nx = MAXT sentinel; needs full cw<0 check) ----
        if (w == NW - 1) {
            const float x  = __int_as_float(pc.x);
            const int  off = pc.y;
            const float nx = MAXT;
            const ull w2 = *reinterpret_cast<const ull*>(Wb + off);
            cw2 = f2_add(cw2, w2);
            ct2 = f2_fma(w2, f2_bcast(x), ct2);
            float cw0, cw1, ct0, ct1;
            f2_unpack(cw0, cw1, cw2);
            f2_unpack(ct0, ct1, ct2);
            {
                float cand = __fdividef(ct0, fmaxf(cw0, EPSV));
                bool bad = (cw0 < 0.f) | (cand < x) | (cand > nx);
                best0 = fminf(best0, bad ? MAXT : cand);
            }
            {
                float cand = __fdividef(ct1, fmaxf(cw1, EPSV));
                bool bad = (cw1 < 0.f) | (cand < x) | (cand > nx);
                best1 = fminf(best1, bad ? MAXT : cand);
            }
        }
        pm[w][2 * lane]     = best0;
        pm[w][2 * lane + 1] = best1;
        __syncthreads();

        // ---- final min across chunks ----
        if (threadIdx.x < MBLK) {
            float bb = MAXT;
            #pragma unroll
            for (int c = 0; c < NW; ++c)
                bb = fminf(bb, pm[c][threadIdx.x]);
            out[b * OUT_SZ + mbase + threadIdx.x] = bb;
        }
        __syncthreads();
    }
}

// ---------------------------------------------------------------------------
extern "C" void kernel_launch(void* const* d_in, const int* in_sizes, int n_in,
                              void* d_out, int out_size) {
    const float* X = (const float*)d_in[0];
    const float* W = (const float*)d_in[1];
    if (n_in >= 2 && in_sizes[0] != BATCH * IN_SZ && in_sizes[1] == BATCH * IN_SZ) {
        X = (const float*)d_in[1];
        W = (const float*)d_in[0];
    }
    float* out = (float*)d_out;

    dim3 gs((KTOT + SORT_ELEMS - 1) / SORT_ELEMS, BATCH);   // (17, 64)
    snn_sort_kernel<<<gs, SORT_BLOCK>>>(X);

    snn_scan_kernel<<<GRID_SCAN, 512>>>(W, out);
}